// round 1
// baseline (speedup 1.0000x reference)
#include <cuda_runtime.h>
#include <math.h>

#define BB 2
#define LL 225
#define DD 256
#define HH 4
#define HD 64
#define BH (BB*HH)
#define NROW (BB*LL)   // 450
#define RHO 0.1f

// ---------------- scratch (device globals; no allocation allowed) ----------
__device__ float g_q[BH*LL*HD];
__device__ float g_k[BH*LL*HD];
__device__ float g_v[BH*LL*HD];
__device__ float g_S[BH*LL*LL];
__device__ float g_A[BH*LL*LL];   // A, later overwritten with A_hat
__device__ float g_dis[BH*LL];
__device__ float g_T[BH*LL*LL];   // T = A_hat @ S
__device__ float g_P[BH*LL*LL];   // S_jump, then attn (softmaxed in place)
__device__ float g_O[BB*LL*DD];   // attn @ v, merged heads [b, l, h*64+dd]

// ---------------- K1: q,k,v projections (y = x @ W^T) ----------------------
// grid (24, 15), block (32,32). columns 0..767 = [Wq | Wk | Wv]
__global__ void qkv_kernel(const float* __restrict__ x,
                           const float* __restrict__ Wq,
                           const float* __restrict__ Wk,
                           const float* __restrict__ Wv) {
    __shared__ float xs[32][33];
    __shared__ float ws[32][33];
    int tx = threadIdx.x, ty = threadIdx.y;
    int r  = blockIdx.y * 32 + ty;
    int c0 = blockIdx.x * 32;
    const float* W = (c0 < 256) ? Wq : (c0 < 512) ? Wk : Wv;
    int o0 = c0 & 255;
    float acc = 0.f;
    for (int k0 = 0; k0 < 256; k0 += 32) {
        xs[ty][tx] = (r < NROW) ? x[r*256 + k0 + tx] : 0.f;
        ws[ty][tx] = W[(o0 + ty)*256 + k0 + tx];
        __syncthreads();
#pragma unroll
        for (int kk = 0; kk < 32; kk++) acc += xs[ty][kk] * ws[tx][kk];
        __syncthreads();
    }
    if (r < NROW) {
        int b = r / LL, l = r % LL;
        int c = c0 + tx;
        int which = c >> 8;
        int oo = c & 255;
        int h = oo >> 6, dd = oo & 63;
        float* dst = (which == 0) ? g_q : (which == 1) ? g_k : g_v;
        dst[((b*HH + h)*LL + l)*HD + dd] = acc;
    }
}

// ---------------- K2: S = q @ k^T per (b,h) --------------------------------
// grid (8, 8, 8), block (32,32)
__global__ void s_kernel() {
    __shared__ float qs[32][33], ks[32][33];
    int bh = blockIdx.z;
    int i0 = blockIdx.y * 32, j0 = blockIdx.x * 32;
    int tx = threadIdx.x, ty = threadIdx.y;
    const float* qb = g_q + bh*LL*HD;
    const float* kb = g_k + bh*LL*HD;
    float acc = 0.f;
    for (int k0 = 0; k0 < HD; k0 += 32) {
        int i = i0 + ty, j = j0 + ty;
        qs[ty][tx] = (i < LL) ? qb[i*HD + k0 + tx] : 0.f;
        ks[ty][tx] = (j < LL) ? kb[j*HD + k0 + tx] : 0.f;
        __syncthreads();
#pragma unroll
        for (int kk = 0; kk < 32; kk++) acc += qs[ty][kk] * ks[tx][kk];
        __syncthreads();
    }
    int i = i0 + ty, j = j0 + tx;
    if (i < LL && j < LL) g_S[bh*LL*LL + i*LL + j] = acc;
}

// ---------------- K3: adjacency A[i,k] = (1/L) sum_j g(S[i,j]S[k,j]/d) -----
// grid (8, 8, 8), block (16,16), 2x2 per thread
__global__ void a_kernel() {
    __shared__ float si[32][33], sk[32][33];
    int bh = blockIdx.z;
    int i0 = blockIdx.y * 32, k0 = blockIdx.x * 32;
    int tx = threadIdx.x, ty = threadIdx.y;
    const float* Sb = g_S + bh*LL*LL;
    float a00 = 0.f, a01 = 0.f, a10 = 0.f, a11 = 0.f;
    for (int j0 = 0; j0 < LL; j0 += 32) {
        int t = ty * 16 + tx;
#pragma unroll
        for (int e = 0; e < 4; e++) {
            int idx = t + e*256;
            int rr = idx >> 5, cc = idx & 31;
            int i = i0 + rr, j = j0 + cc, k = k0 + rr;
            si[rr][cc] = (i < LL && j < LL) ? Sb[i*LL + j] : 0.f;
            sk[rr][cc] = (k < LL && j < LL) ? Sb[k*LL + j] : 0.f;
        }
        __syncthreads();
#pragma unroll
        for (int jj = 0; jj < 32; jj++) {
            float ai0 = si[ty][jj],    ai1 = si[ty+16][jj];
            float bk0 = sk[tx][jj],    bk1 = sk[tx+16][jj];
            float u;
            u = ai0*bk0*(1.f/64.f); a00 += (u > RHO) ? u : 0.f;
            u = ai0*bk1*(1.f/64.f); a01 += (u > RHO) ? u : 0.f;
            u = ai1*bk0*(1.f/64.f); a10 += (u > RHO) ? u : 0.f;
            u = ai1*bk1*(1.f/64.f); a11 += (u > RHO) ? u : 0.f;
        }
        __syncthreads();
    }
    float* Ab = g_A + bh*LL*LL;
    const float invL = 1.f / (float)LL;
    int i, k;
    i = i0+ty;    k = k0+tx;    if (i<LL && k<LL) Ab[i*LL+k] = (i==k)?0.f:a00*invL;
    i = i0+ty;    k = k0+tx+16; if (i<LL && k<LL) Ab[i*LL+k] = (i==k)?0.f:a01*invL;
    i = i0+ty+16; k = k0+tx;    if (i<LL && k<LL) Ab[i*LL+k] = (i==k)?0.f:a10*invL;
    i = i0+ty+16; k = k0+tx+16; if (i<LL && k<LL) Ab[i*LL+k] = (i==k)?0.f:a11*invL;
}

// ---------------- K4a: degree -> d^{-1/2}, one warp per row ----------------
// grid 225, block 256 (8 warps)
__global__ void deg_kernel() {
    int w = threadIdx.x >> 5, lane = threadIdx.x & 31;
    int row = blockIdx.x * 8 + w;             // 0..1799
    if (row >= BH*LL) return;
    const float* Ar = g_A + row * LL;         // row = bh*L + i; A row base = bh*L*L + i*L
    float s = 0.f;
    for (int k = lane; k < LL; k += 32) s += Ar[k];
#pragma unroll
    for (int off = 16; off > 0; off >>= 1) s += __shfl_xor_sync(0xffffffffu, s, off);
    if (lane == 0) {
        float deg = fmaxf(1.f + s, 1e-6f);
        g_dis[row] = 1.f / sqrtf(deg);
    }
}

// ---------------- K4b: A_hat = dis[i]*(A + I)*dis[k] in place --------------
__global__ void ahat_kernel() {
    int idx = blockIdx.x * blockDim.x + threadIdx.x;
    if (idx >= BH*LL*LL) return;
    int bh = idx / (LL*LL);
    int rem = idx % (LL*LL);
    int i = rem / LL, k = rem % LL;
    float a = g_A[idx] + ((i == k) ? 1.f : 0.f);
    g_A[idx] = a * g_dis[bh*LL + i] * g_dis[bh*LL + k];
}

// ---------------- K5/K6: 225x225x225 GEMMs ---------------------------------
// MODE 0: T = A_hat @ S                 (scale 1)
// MODE 1: P = T @ A_hat^T / sqrt(64)    (scale 0.125)
// grid (8, 8, 8), block (16,16), 2x2 per thread
template<int MODE>
__global__ void gemm225_kernel() {
    __shared__ float as[32][33], bs[32][33];
    int bh = blockIdx.z;
    int i0 = blockIdx.y * 32, j0 = blockIdx.x * 32;
    int tx = threadIdx.x, ty = threadIdx.y;
    const float* Ab = ((MODE == 0) ? g_A : g_T) + bh*LL*LL;
    const float* Bb = ((MODE == 0) ? g_S : g_A) + bh*LL*LL;
    float*       Cb = ((MODE == 0) ? g_T : g_P) + bh*LL*LL;
    const float scale = (MODE == 0) ? 1.f : 0.125f;
    float c00 = 0.f, c01 = 0.f, c10 = 0.f, c11 = 0.f;
    for (int k0 = 0; k0 < LL; k0 += 32) {
        int t = ty * 16 + tx;
#pragma unroll
        for (int e = 0; e < 4; e++) {
            int idx = t + e*256;
            int rr = idx >> 5, cc = idx & 31;
            int i = i0 + rr, kc = k0 + cc;
            as[rr][cc] = (i < LL && kc < LL) ? Ab[i*LL + kc] : 0.f;
            if (MODE == 1) {
                // B^T: bs[kk][c] = B[j0+c][k0+kk]; load row j0+rr, cols k0+cc
                int j = j0 + rr;
                bs[cc][rr] = (j < LL && kc < LL) ? Bb[j*LL + kc] : 0.f;
            } else {
                int kr = k0 + rr, j = j0 + cc;
                bs[rr][cc] = (kr < LL && j < LL) ? Bb[kr*LL + j] : 0.f;
            }
        }
        __syncthreads();
#pragma unroll
        for (int kk = 0; kk < 32; kk++) {
            float a0 = as[ty][kk],    a1 = as[ty+16][kk];
            float b0 = bs[kk][tx],    b1 = bs[kk][tx+16];
            c00 += a0*b0; c01 += a0*b1; c10 += a1*b0; c11 += a1*b1;
        }
        __syncthreads();
    }
    int i, j;
    i = i0+ty;    j = j0+tx;    if (i<LL && j<LL) Cb[i*LL+j] = c00*scale;
    i = i0+ty;    j = j0+tx+16; if (i<LL && j<LL) Cb[i*LL+j] = c01*scale;
    i = i0+ty+16; j = j0+tx;    if (i<LL && j<LL) Cb[i*LL+j] = c10*scale;
    i = i0+ty+16; j = j0+tx+16; if (i<LL && j<LL) Cb[i*LL+j] = c11*scale;
}

// ---------------- K7: row softmax of P in place (one warp per row) ---------
__global__ void softmax_kernel() {
    int w = threadIdx.x >> 5, lane = threadIdx.x & 31;
    int row = blockIdx.x * 8 + w;
    if (row >= BH*LL) return;
    float* Pr = g_P + row * LL;
    float vals[8];
    float mx = -1e30f;
#pragma unroll
    for (int e = 0; e < 8; e++) {
        int j = lane + e*32;
        vals[e] = (j < LL) ? Pr[j] : -1e30f;
        mx = fmaxf(mx, vals[e]);
    }
#pragma unroll
    for (int off = 16; off > 0; off >>= 1) mx = fmaxf(mx, __shfl_xor_sync(0xffffffffu, mx, off));
    float s = 0.f;
#pragma unroll
    for (int e = 0; e < 8; e++) {
        int j = lane + e*32;
        vals[e] = expf(vals[e] - mx);
        if (j < LL) s += vals[e];
    }
#pragma unroll
    for (int off = 16; off > 0; off >>= 1) s += __shfl_xor_sync(0xffffffffu, s, off);
    float inv = 1.f / s;
#pragma unroll
    for (int e = 0; e < 8; e++) {
        int j = lane + e*32;
        if (j < LL) Pr[j] = vals[e] * inv;
    }
}

// ---------------- K8: O = attn @ v, merge heads ----------------------------
// grid (2, 8, 8), block (16,16), 2x2 per thread
__global__ void av_kernel() {
    __shared__ float ps[32][33], vs[32][33];
    int bh = blockIdx.z;
    int i0 = blockIdx.y * 32, j0 = blockIdx.x * 32;   // j0 in {0, 32}
    int tx = threadIdx.x, ty = threadIdx.y;
    const float* Pb = g_P + bh*LL*LL;
    const float* Vb = g_v + bh*LL*HD;
    float c00 = 0.f, c01 = 0.f, c10 = 0.f, c11 = 0.f;
    for (int k0 = 0; k0 < LL; k0 += 32) {
        int t = ty * 16 + tx;
#pragma unroll
        for (int e = 0; e < 4; e++) {
            int idx = t + e*256;
            int rr = idx >> 5, cc = idx & 31;
            int i = i0 + rr, kc = k0 + cc;
            ps[rr][cc] = (i < LL && kc < LL) ? Pb[i*LL + kc] : 0.f;
            int kr = k0 + rr;
            vs[rr][cc] = (kr < LL) ? Vb[kr*HD + j0 + cc] : 0.f;
        }
        __syncthreads();
#pragma unroll
        for (int kk = 0; kk < 32; kk++) {
            float a0 = ps[ty][kk],    a1 = ps[ty+16][kk];
            float b0 = vs[kk][tx],    b1 = vs[kk][tx+16];
            c00 += a0*b0; c01 += a0*b1; c10 += a1*b0; c11 += a1*b1;
        }
        __syncthreads();
    }
    int b = bh / HH, h = bh % HH;
    int i, dd;
    i = i0+ty;    dd = j0+tx;    if (i<LL) g_O[(b*LL+i)*DD + h*HD + dd] = c00;
    i = i0+ty;    dd = j0+tx+16; if (i<LL) g_O[(b*LL+i)*DD + h*HD + dd] = c01;
    i = i0+ty+16; dd = j0+tx;    if (i<LL) g_O[(b*LL+i)*DD + h*HD + dd] = c10;
    i = i0+ty+16; dd = j0+tx+16; if (i<LL) g_O[(b*LL+i)*DD + h*HD + dd] = c11;
}

// ---------------- K9: out = O @ Wo^T ---------------------------------------
// grid (8, 15), block (32,32)
__global__ void out_kernel(const float* __restrict__ Wo, float* __restrict__ out) {
    __shared__ float xs[32][33], ws[32][33];
    int tx = threadIdx.x, ty = threadIdx.y;
    int r  = blockIdx.y * 32 + ty;
    int c0 = blockIdx.x * 32;
    float acc = 0.f;
    for (int k0 = 0; k0 < 256; k0 += 32) {
        xs[ty][tx] = (r < NROW) ? g_O[r*256 + k0 + tx] : 0.f;
        ws[ty][tx] = Wo[(c0 + ty)*256 + k0 + tx];
        __syncthreads();
#pragma unroll
        for (int kk = 0; kk < 32; kk++) acc += xs[ty][kk] * ws[tx][kk];
        __syncthreads();
    }
    if (r < NROW) out[r*256 + c0 + tx] = acc;
}

// ---------------- launcher --------------------------------------------------
extern "C" void kernel_launch(void* const* d_in, const int* in_sizes, int n_in,
                              void* d_out, int out_size) {
    const float* x  = (const float*)d_in[0];
    const float* Wq = (const float*)d_in[1];
    const float* Wk = (const float*)d_in[2];
    const float* Wv = (const float*)d_in[3];
    const float* Wo = (const float*)d_in[4];
    float* out = (float*)d_out;

    dim3 blk32(32, 32), blk16(16, 16);

    qkv_kernel<<<dim3(24, 15), blk32>>>(x, Wq, Wk, Wv);
    s_kernel<<<dim3(8, 8, 8), blk32>>>();
    a_kernel<<<dim3(8, 8, 8), blk16>>>();
    deg_kernel<<<225, 256>>>();
    ahat_kernel<<<(BH*LL*LL + 255) / 256, 256>>>();
    gemm225_kernel<0><<<dim3(8, 8, 8), blk16>>>();
    gemm225_kernel<1><<<dim3(8, 8, 8), blk16>>>();
    softmax_kernel<<<225, 256>>>();
    av_kernel<<<dim3(2, 8, 8), blk16>>>();
    out_kernel<<<dim3(8, 15), blk32>>>(Wo, out);
}